// round 16
// baseline (speedup 1.0000x reference)
#include <cuda_runtime.h>
#include <cuda_fp16.h>
#include <cstddef>
#include <cstdint>

#define BATCH   16
#define CIN     256
#define NPIX    1024
#define HEADS   8
#define DH      64
#define INNER   512
#define MQKV    1536
#define OUT_ELEMS   (BATCH * CIN * NPIX)            // 4194304

// Scratch (device globals: allocation-free rule) — fp16 intermediates
__device__ __half g_qkvT[(size_t)BATCH * NPIX * MQKV];   // [b][p][1536] q|k|v (d-contig)
__device__ __half g_xh  [(size_t)BATCH * NPIX * CIN ];   // [b][p][c]
__device__ __half g_ctxh[(size_t)BATCH * NPIX * INNER];  // [b][p][hd]
__device__ __half g_wh  [(size_t)MQKV * CIN ];           // [1536][256] (Wq|Wkv)
__device__ __half g_woh [(size_t)CIN  * INNER];          // [256][512]

// ---------------------------------------------------------------------------
// cp.async helpers
// ---------------------------------------------------------------------------
__device__ __forceinline__ void cp16(uint32_t dst, const void* src) {
    asm volatile("cp.async.cg.shared.global [%0], [%1], 16;" :: "r"(dst), "l"(src));
}
__device__ __forceinline__ void cp16z(uint32_t dst, const void* src, bool ok) {
    int sz = ok ? 16 : 0;
    asm volatile("cp.async.cg.shared.global [%0], [%1], 16, %2;"
                 :: "r"(dst), "l"(src), "r"(sz));
}
__device__ __forceinline__ void cp_commit() {
    asm volatile("cp.async.commit_group;" ::: "memory");
}
__device__ __forceinline__ void cp_wait1() {
    asm volatile("cp.async.wait_group 1;" ::: "memory");
}
__device__ __forceinline__ void cp_wait2() {
    asm volatile("cp.async.wait_group 2;" ::: "memory");
}
__device__ __forceinline__ void ldm_x4(uint32_t r[4], uint32_t saddr) {
    asm volatile("ldmatrix.sync.aligned.m8n8.x4.shared.b16 {%0,%1,%2,%3}, [%4];"
        : "=r"(r[0]), "=r"(r[1]), "=r"(r[2]), "=r"(r[3]) : "r"(saddr));
}
__device__ __forceinline__ void mma_f16(float c[4], const uint32_t a[4], const uint32_t b[2]) {
    asm volatile(
        "mma.sync.aligned.m16n8k16.row.col.f32.f16.f16.f32 "
        "{%0,%1,%2,%3},{%4,%5,%6,%7},{%8,%9},{%0,%1,%2,%3};"
        : "+f"(c[0]), "+f"(c[1]), "+f"(c[2]), "+f"(c[3])
        : "r"(a[0]), "r"(a[1]), "r"(a[2]), "r"(a[3]), "r"(b[0]), "r"(b[1]));
}

// ---------------------------------------------------------------------------
// Prep 1: transpose + fp16-round x: [b][c][p] -> g_xh[b][p][c]
// ---------------------------------------------------------------------------
__global__ void __launch_bounds__(256)
prep_x(const float* __restrict__ x)
{
    __shared__ float sm[32][33];
    const int b = blockIdx.z, ct = blockIdx.y, pt = blockIdx.x;
    const int t = threadIdx.x;
    const float* xb = x + ((size_t)b * CIN + ct * 32) * NPIX + pt * 32;
    const int cl = t >> 5, pl = t & 31;
    #pragma unroll
    for (int i = 0; i < 4; i++)
        sm[cl + i * 8][pl] = xb[(size_t)(cl + i * 8) * NPIX + pl];
    __syncthreads();
    __half* xo = g_xh + ((size_t)b * NPIX + pt * 32) * CIN + ct * 32;
    const int pr = t >> 5, cc = t & 31;
    #pragma unroll
    for (int i = 0; i < 4; i++)
        xo[(size_t)(pr + i * 8) * CIN + cc] = __float2half_rn(sm[cc][pr + i * 8]);
}

// ---------------------------------------------------------------------------
// Prep 2: fp16-round weights into g_wh (Wq|Wkv) and g_woh.
// ---------------------------------------------------------------------------
__global__ void __launch_bounds__(256)
prep_w(const float* __restrict__ Wq, const float* __restrict__ Wkv,
       const float* __restrict__ Wo)
{
    const int i = blockIdx.x * 256 + threadIdx.x;   // float4 index, grid covers 131072
    float4 v; __half* dst;
    if (i < 32768)      { v = ((const float4*)Wq)[i];          dst = g_wh  + (size_t)i * 4; }
    else if (i < 98304) { v = ((const float4*)Wkv)[i - 32768]; dst = g_wh  + (size_t)i * 4; }
    else                { v = ((const float4*)Wo)[i - 98304];  dst = g_woh + (size_t)(i - 98304) * 4; }
    *(half2*)(dst)     = __floats2half2_rn(v.x, v.y);
    *(half2*)(dst + 2) = __floats2half2_rn(v.z, v.w);
}

// ---------------------------------------------------------------------------
// Pipelined FP16 tensor-core GEMM (mma.m16n8k16, f32 accum) — unchanged R14.
// ---------------------------------------------------------------------------
#define BKH 64
#define RSB 144
#define TILE_BH (128 * RSB)
#define STAGE_BH (2 * TILE_BH)
#define SMEM_GH (2 * STAGE_BH)       // 73728 B

extern __shared__ uint8_t g_dsmem[];

__global__ void __launch_bounds__(256, 2)
gemm_h(int a_sel, int b_sel, float* __restrict__ Cext, int c_sel,
       const float* __restrict__ bias, int M, int K)
{
    const int n0 = blockIdx.x * 128;
    const int m0 = blockIdx.y * 128;
    const int z  = blockIdx.z;

    const __half* __restrict__ A  = (a_sel == 1) ? g_wh : g_woh;
    const __half* __restrict__ Bm = (b_sel == 1) ? g_xh : g_ctxh;

    const __half* __restrict__ Ab = A + (size_t)m0 * K;
    const __half* __restrict__ Bb = Bm + ((size_t)z * NPIX + n0) * K;

    float* Cf = Cext + (size_t)z * CIN * NPIX + (size_t)m0 * NPIX + n0;

    const uint32_t sbase = (uint32_t)__cvta_generic_to_shared(g_dsmem);

    const int tid  = threadIdx.x;
    const int lane = tid & 31;
    const int warp = tid >> 5;
    const int wm0  = (warp >> 1) * 32;
    const int wn0  = (warp & 1) * 64;
    const int grp  = lane >> 2;
    const int qid  = lane & 3;

    const int sr  = tid >> 3;
    const int seg = tid & 7;

    const int a_r = ((lane >> 3) & 1) * 8 + (lane & 7);
    const int a_k = ((lane >> 4) & 1) * 16;
    const int b_r = ((lane >> 4) & 1) * 8 + (lane & 7);
    const int b_k = ((lane >> 3) & 1) * 16;

    float acc[2][8][4];
    #pragma unroll
    for (int mt = 0; mt < 2; mt++)
        #pragma unroll
        for (int j = 0; j < 8; j++)
            #pragma unroll
            for (int e = 0; e < 4; e++) acc[mt][j][e] = 0.f;

    const int NT = K / BKH;

    auto stage = [&](int kt, int s) {
        const uint32_t aB = sbase + s * STAGE_BH;
        const uint32_t bB = aB + TILE_BH;
        const int kh = kt * BKH + seg * 8;
        #pragma unroll
        for (int it = 0; it < 4; it++) {
            int r = sr + it * 32;
            cp16(aB + r * RSB + seg * 16, Ab + (size_t)r * K + kh);
            cp16(bB + r * RSB + seg * 16, Bb + (size_t)r * K + kh);
        }
    };

    stage(0, 0);
    cp_commit();

    for (int kt = 0; kt < NT; kt++) {
        if (kt + 1 < NT) stage(kt + 1, (kt + 1) & 1);
        cp_commit();
        cp_wait1();
        __syncthreads();

        const uint32_t aS = sbase + (kt & 1) * STAGE_BH;
        const uint32_t bS = aS + TILE_BH;

        #pragma unroll
        for (int s = 0; s < 4; s++) {
            const int kb = s * 32;
            uint32_t afr[2][4];
            #pragma unroll
            for (int mt = 0; mt < 2; mt++)
                ldm_x4(afr[mt], aS + (wm0 + mt * 16 + a_r) * RSB + kb + a_k);
            uint32_t bfr[8][2];
            #pragma unroll
            for (int jj = 0; jj < 4; jj++) {
                uint32_t r[4];
                ldm_x4(r, bS + (wn0 + jj * 16 + b_r) * RSB + kb + b_k);
                bfr[jj * 2 + 0][0] = r[0]; bfr[jj * 2 + 0][1] = r[1];
                bfr[jj * 2 + 1][0] = r[2]; bfr[jj * 2 + 1][1] = r[3];
            }
            #pragma unroll
            for (int mt = 0; mt < 2; mt++)
                #pragma unroll
                for (int j = 0; j < 8; j++)
                    mma_f16(acc[mt][j], afr[mt], bfr[j]);
        }
        __syncthreads();
    }

    if (c_sel == 1) {
        // Transposed epilogue: smem bounce [n=128][m=136 halves], then
        // coalesced 16B stores: 128 rows x 16 uint4-segments = 2048 uint4.
        __half* To = (__half*)g_dsmem;     // [128][136]
        #pragma unroll
        for (int mt = 0; mt < 2; mt++)
            #pragma unroll
            for (int e2 = 0; e2 < 2; e2++) {
                int m = wm0 + mt * 16 + grp + e2 * 8;
                #pragma unroll
                for (int j = 0; j < 8; j++) {
                    int n = wn0 + j * 8 + 2 * qid;
                    To[(n + 0) * 136 + m] = __float2half_rn(acc[mt][j][e2 * 2 + 0]);
                    To[(n + 1) * 136 + m] = __float2half_rn(acc[mt][j][e2 * 2 + 1]);
                }
            }
        __syncthreads();
        __half* base = g_qkvT + ((size_t)z * NPIX + n0) * MQKV + m0;
        #pragma unroll
        for (int i = 0; i < 8; i++) {
            int idx = tid + i * 256;        // 0..2047
            int n  = idx >> 4;              // 0..127
            int sg = idx & 15;              // 0..15
            uint4 val = *(uint4*)(To + n * 136 + sg * 8);
            *(uint4*)(base + (size_t)n * MQKV + sg * 8) = val;
        }
    } else {
        #pragma unroll
        for (int mt = 0; mt < 2; mt++)
            #pragma unroll
            for (int e2 = 0; e2 < 2; e2++) {
                int mloc = wm0 + mt * 16 + grp + e2 * 8;
                float bv = bias[m0 + mloc];
                #pragma unroll
                for (int j = 0; j < 8; j++) {
                    float2 r;
                    r.x = acc[mt][j][e2 * 2 + 0] + bv;
                    r.y = acc[mt][j][e2 * 2 + 1] + bv;
                    *(float2*)(Cf + (size_t)mloc * NPIX + wn0 + j * 8 + 2 * qid) = r;
                }
            }
    }
}

// ---------------------------------------------------------------------------
// 3x3 windowed attention — d-contiguous uint4 tiles, k AND v as 4-deep rings
// (43.5 KB smem -> 5 blocks/SM -> the whole 512-block grid is one resident
// wave). Seamless handoff: pass-1 iters 6,7 stage v0,v1 so softmax overlaps
// v staging; uniform wait_group 2 ledger throughout. 1 __syncthreads per
// iteration (ring target last read two syncs ago). cp.async zfill covers all
// halo/OOB -> exact zero-pad semantics (OOB logit contribution 0).
// ---------------------------------------------------------------------------
#define TPOS 340                          // 10*34 positions per chunk
#define RING 4
#define ATT_SMEM (2 * RING * TPOS * 16)   // 43520 B

__global__ void __launch_bounds__(256)
attn_kernel(float* __restrict__ attn_out)
{
    uint4* tk4 = (uint4*)g_dsmem;          // [4][340]  k ring
    uint4* tv4 = tk4 + RING * TPOS;        // [4][340]  v ring

    const int tid  = threadIdx.x;
    const int lane = tid & 31;
    const int warp = tid >> 5;
    const int ry   = warp;                 // row within slab
    const int x    = lane;                 // col
    const int r0   = blockIdx.x * 8;
    const int h    = blockIdx.y;
    const int b    = blockIdx.z;
    const int p    = (r0 + ry) * 32 + x;

    const __half* __restrict__ qT = g_qkvT + ((size_t)(b * NPIX + p)) * MQKV + h * DH;
    const __half* __restrict__ kBase = g_qkvT + (size_t)b * NPIX * MQKV + 512 + h * DH;
    const __half* __restrict__ vBase = kBase + 512;

    const int bidx = ry * 34 + x;          // this thread's tile position

    // stage one chunk (dc..dc+7) of src (k or v) into dstbuf (uint4[340])
    auto stageChunk = [&](const __half* __restrict__ src, int dc, uint4* dstbuf) {
        const uint32_t dsb = (uint32_t)__cvta_generic_to_shared(dstbuf);
        #pragma unroll
        for (int rep = 0; rep < 2; rep++) {
            const int rr = warp + rep * 8;
            if (rep == 0 || warp < 2) {
                const int gy = r0 + rr - 1;
                const bool rok = ((unsigned)gy < 32u);
                {
                    const int gx = lane - 1;
                    const bool ok = rok && ((unsigned)gx < 32u);
                    const __half* s = src + (ok ? (size_t)(gy * 32 + gx) * MQKV : 0) + dc;
                    cp16z(dsb + (uint32_t)((rr * 34 + lane) * 16), s, ok);
                }
                if (lane < 2) {
                    const int gx = lane + 31;
                    const bool ok = rok && ((unsigned)gx < 32u);
                    const __half* s = src + (ok ? (size_t)(gy * 32 + gx) * MQKV : 0) + dc;
                    cp16z(dsb + (uint32_t)((rr * 34 + lane + 32) * 16), s, ok);
                }
            }
        }
    };

    // window offsets in uint4 units
    const int WOFF[9] = {0, 1, 2, 34, 35, 36, 68, 69, 70};

    // ---------------- Pass 1: dots = q . k  (v0,v1 staged at tail) --------
    float dots[9];
    #pragma unroll
    for (int w = 0; w < 9; w++) dots[w] = 0.f;

    stageChunk(kBase, 0, tk4);          cp_commit();   // g0
    stageChunk(kBase, 8, tk4 + TPOS);   cp_commit();   // g1

    #pragma unroll 1
    for (int c = 0; c < 8; c++) {
        if (c + 2 < 8) stageChunk(kBase, (c + 2) * 8, tk4 + ((c + 2) & 3) * TPOS);
        else           stageChunk(vBase, (c - 6) * 8, tv4 + (c - 6) * TPOS);
        cp_commit();                   // g_{c+2}
        cp_wait2();                    // group c complete (own copies)
        __syncthreads();               // all threads waited -> visible

        const uint4* kB = tk4 + (c & 3) * TPOS;
        uint4 q4 = *(const uint4*)(qT + c * 8);
        half2 qh[4];
        *(uint4*)qh = q4;
        #pragma unroll
        for (int w = 0; w < 9; w++) {
            uint4 kv = kB[bidx + WOFF[w]];
            half2 kh[4];
            *(uint4*)kh = kv;
            half2 s = __hmul2(qh[0], kh[0]);
            s = __hfma2(qh[1], kh[1], s);
            s = __hfma2(qh[2], kh[2], s);
            s = __hfma2(qh[3], kh[3], s);
            float2 f = __half22float2(s);
            dots[w] += f.x + f.y;
        }
    }

    // softmax over 9 (OOB logits exactly 0) — overlaps v0/v1 staging
    const float scale = 0.125f;
    float mx = -1e30f;
    #pragma unroll
    for (int w = 0; w < 9; w++) { dots[w] *= scale; mx = fmaxf(mx, dots[w]); }
    float a[9], sum = 0.f;
    #pragma unroll
    for (int w = 0; w < 9; w++) { a[w] = expf(dots[w] - mx); sum += a[w]; }
    float inv = 1.f / sum;
    #pragma unroll
    for (int w = 0; w < 9; w++) a[w] *= inv;

    {
        float* ao = attn_out + ((size_t)(b * HEADS + h) * NPIX + p) * 9;
        #pragma unroll
        for (int w = 0; w < 9; w++) ao[w] = a[w];
    }

    // ---------------- Pass 2: ctx = attn . v  (v ring continues) ----------
    __half* __restrict__ ct = g_ctxh + ((size_t)b * NPIX + p) * INNER + h * DH;

    #pragma unroll 1
    for (int c = 0; c < 8; c++) {
        if (c + 2 < 8) stageChunk(vBase, (c + 2) * 8, tv4 + ((c + 2) & 3) * TPOS);
        cp_commit();                   // g_{10+c} (empty for c>=6)
        cp_wait2();                    // v_c (= g_{8+c}) complete
        __syncthreads();

        const uint4* vB = tv4 + (c & 3) * TPOS;
        float acc8[8];
        #pragma unroll
        for (int d = 0; d < 8; d++) acc8[d] = 0.f;
        #pragma unroll
        for (int w = 0; w < 9; w++) {
            uint4 vv = vB[bidx + WOFF[w]];
            half2 vh[4];
            *(uint4*)vh = vv;
            #pragma unroll
            for (int j = 0; j < 4; j++) {
                float2 f = __half22float2(vh[j]);
                acc8[2 * j + 0] += a[w] * f.x;
                acc8[2 * j + 1] += a[w] * f.y;
            }
        }
        half2 hout[4];
        #pragma unroll
        for (int j = 0; j < 4; j++)
            hout[j] = __floats2half2_rn(acc8[2 * j], acc8[2 * j + 1]);
        *(uint4*)(ct + c * 8) = *(uint4*)hout;
    }
}

// ---------------------------------------------------------------------------
extern "C" void kernel_launch(void* const* d_in, const int* in_sizes, int n_in,
                              void* d_out, int out_size)
{
    const float* x   = (const float*)d_in[0];
    const float* Wq  = (const float*)d_in[1];
    const float* Wkv = (const float*)d_in[2];
    const float* Wo  = (const float*)d_in[3];
    const float* bo  = (const float*)d_in[4];
    float* out = (float*)d_out;     // out (4194304) | attn (1179648)

    static int smem_set = 0;
    if (!smem_set) {
        cudaFuncSetAttribute(gemm_h, cudaFuncAttributeMaxDynamicSharedMemorySize,
                             SMEM_GH);
        cudaFuncSetAttribute(attn_kernel, cudaFuncAttributeMaxDynamicSharedMemorySize,
                             ATT_SMEM);
        smem_set = 1;
    }

    // prep: transpose+round x, round weights (fp16)
    {
        dim3 g(32, 8, BATCH);
        prep_x<<<g, 256>>>(x);
        prep_w<<<512, 256>>>(Wq, Wkv, Wo);
    }

    // QKV: g_qkvT[b][p][m] = g_wh[m][:] . g_xh[b][p][:]   (K=256, NT=4)
    {
        dim3 grid(NPIX / 128, MQKV / 128, BATCH);   // (8, 12, 16)
        gemm_h<<<grid, 256, SMEM_GH>>>(1, 1, nullptr, 1, nullptr, MQKV, CIN);
    }

    // attention -> attn tail + g_ctxh
    {
        dim3 grid(4, HEADS, BATCH);                 // 512 blocks, single wave
        attn_kernel<<<grid, 256, ATT_SMEM>>>(out + OUT_ELEMS);
    }

    // out projection: out[b][c][p] = g_woh[c][:] . g_ctxh[b][p][:] + bo[c]  (K=512, NT=8)
    {
        dim3 grid(NPIX / 128, CIN / 128, BATCH);    // (8, 2, 16)
        gemm_h<<<grid, 256, SMEM_GH>>>(2, 2, out, 0, bo, CIN, INNER);
    }
}

// round 17
// speedup vs baseline: 1.0595x; 1.0595x over previous
#include <cuda_runtime.h>
#include <cuda_fp16.h>
#include <cstddef>
#include <cstdint>

#define BATCH   16
#define CIN     256
#define NPIX    1024
#define HEADS   8
#define DH      64
#define INNER   512
#define MQKV    1536
#define OUT_ELEMS   (BATCH * CIN * NPIX)            // 4194304

// Scratch (device globals: allocation-free rule) — fp16 intermediates
__device__ __half g_qkvT[(size_t)BATCH * NPIX * MQKV];   // [b][p][1536] q|k|v (d-contig)
__device__ __half g_xh  [(size_t)BATCH * NPIX * CIN ];   // [b][p][c]
__device__ __half g_ctxh[(size_t)BATCH * NPIX * INNER];  // [b][p][hd]
__device__ __half g_wh  [(size_t)MQKV * CIN ];           // [1536][256] (Wq|Wkv)
__device__ __half g_woh [(size_t)CIN  * INNER];          // [256][512]

// ---------------------------------------------------------------------------
// cp.async helpers
// ---------------------------------------------------------------------------
__device__ __forceinline__ void cp16(uint32_t dst, const void* src) {
    asm volatile("cp.async.cg.shared.global [%0], [%1], 16;" :: "r"(dst), "l"(src));
}
__device__ __forceinline__ void cp16z(uint32_t dst, const void* src, bool ok) {
    int sz = ok ? 16 : 0;
    asm volatile("cp.async.cg.shared.global [%0], [%1], 16, %2;"
                 :: "r"(dst), "l"(src), "r"(sz));
}
__device__ __forceinline__ void cp_commit() {
    asm volatile("cp.async.commit_group;" ::: "memory");
}
__device__ __forceinline__ void cp_wait1() {
    asm volatile("cp.async.wait_group 1;" ::: "memory");
}
__device__ __forceinline__ void cp_wait0() {
    asm volatile("cp.async.wait_group 0;" ::: "memory");
}
__device__ __forceinline__ void ldm_x4(uint32_t r[4], uint32_t saddr) {
    asm volatile("ldmatrix.sync.aligned.m8n8.x4.shared.b16 {%0,%1,%2,%3}, [%4];"
        : "=r"(r[0]), "=r"(r[1]), "=r"(r[2]), "=r"(r[3]) : "r"(saddr));
}
__device__ __forceinline__ void mma_f16(float c[4], const uint32_t a[4], const uint32_t b[2]) {
    asm volatile(
        "mma.sync.aligned.m16n8k16.row.col.f32.f16.f16.f32 "
        "{%0,%1,%2,%3},{%4,%5,%6,%7},{%8,%9},{%0,%1,%2,%3};"
        : "+f"(c[0]), "+f"(c[1]), "+f"(c[2]), "+f"(c[3])
        : "r"(a[0]), "r"(a[1]), "r"(a[2]), "r"(a[3]), "r"(b[0]), "r"(b[1]));
}

// ---------------------------------------------------------------------------
// Prep 1: transpose + fp16-round x: [b][c][p] -> g_xh[b][p][c]
// ---------------------------------------------------------------------------
__global__ void __launch_bounds__(256)
prep_x(const float* __restrict__ x)
{
    __shared__ float sm[32][33];
    const int b = blockIdx.z, ct = blockIdx.y, pt = blockIdx.x;
    const int t = threadIdx.x;
    const float* xb = x + ((size_t)b * CIN + ct * 32) * NPIX + pt * 32;
    const int cl = t >> 5, pl = t & 31;
    #pragma unroll
    for (int i = 0; i < 4; i++)
        sm[cl + i * 8][pl] = xb[(size_t)(cl + i * 8) * NPIX + pl];
    __syncthreads();
    __half* xo = g_xh + ((size_t)b * NPIX + pt * 32) * CIN + ct * 32;
    const int pr = t >> 5, cc = t & 31;
    #pragma unroll
    for (int i = 0; i < 4; i++)
        xo[(size_t)(pr + i * 8) * CIN + cc] = __float2half_rn(sm[cc][pr + i * 8]);
}

// ---------------------------------------------------------------------------
// Prep 2: fp16-round weights into g_wh (Wq|Wkv) and g_woh.
// ---------------------------------------------------------------------------
__global__ void __launch_bounds__(256)
prep_w(const float* __restrict__ Wq, const float* __restrict__ Wkv,
       const float* __restrict__ Wo)
{
    const int i = blockIdx.x * 256 + threadIdx.x;   // float4 index, grid covers 131072
    float4 v; __half* dst;
    if (i < 32768)      { v = ((const float4*)Wq)[i];          dst = g_wh  + (size_t)i * 4; }
    else if (i < 98304) { v = ((const float4*)Wkv)[i - 32768]; dst = g_wh  + (size_t)i * 4; }
    else                { v = ((const float4*)Wo)[i - 98304];  dst = g_woh + (size_t)(i - 98304) * 4; }
    *(half2*)(dst)     = __floats2half2_rn(v.x, v.y);
    *(half2*)(dst + 2) = __floats2half2_rn(v.z, v.w);
}

// ---------------------------------------------------------------------------
// Pipelined FP16 tensor-core GEMM (mma.m16n8k16, f32 accum) — unchanged R14.
// ---------------------------------------------------------------------------
#define BKH 64
#define RSB 144
#define TILE_BH (128 * RSB)
#define STAGE_BH (2 * TILE_BH)
#define SMEM_GH (2 * STAGE_BH)       // 73728 B

extern __shared__ uint8_t g_dsmem[];

__global__ void __launch_bounds__(256, 2)
gemm_h(int a_sel, int b_sel, float* __restrict__ Cext, int c_sel,
       const float* __restrict__ bias, int M, int K)
{
    const int n0 = blockIdx.x * 128;
    const int m0 = blockIdx.y * 128;
    const int z  = blockIdx.z;

    const __half* __restrict__ A  = (a_sel == 1) ? g_wh : g_woh;
    const __half* __restrict__ Bm = (b_sel == 1) ? g_xh : g_ctxh;

    const __half* __restrict__ Ab = A + (size_t)m0 * K;
    const __half* __restrict__ Bb = Bm + ((size_t)z * NPIX + n0) * K;

    float* Cf = Cext + (size_t)z * CIN * NPIX + (size_t)m0 * NPIX + n0;

    const uint32_t sbase = (uint32_t)__cvta_generic_to_shared(g_dsmem);

    const int tid  = threadIdx.x;
    const int lane = tid & 31;
    const int warp = tid >> 5;
    const int wm0  = (warp >> 1) * 32;
    const int wn0  = (warp & 1) * 64;
    const int grp  = lane >> 2;
    const int qid  = lane & 3;

    const int sr  = tid >> 3;
    const int seg = tid & 7;

    const int a_r = ((lane >> 3) & 1) * 8 + (lane & 7);
    const int a_k = ((lane >> 4) & 1) * 16;
    const int b_r = ((lane >> 4) & 1) * 8 + (lane & 7);
    const int b_k = ((lane >> 3) & 1) * 16;

    float acc[2][8][4];
    #pragma unroll
    for (int mt = 0; mt < 2; mt++)
        #pragma unroll
        for (int j = 0; j < 8; j++)
            #pragma unroll
            for (int e = 0; e < 4; e++) acc[mt][j][e] = 0.f;

    const int NT = K / BKH;

    auto stage = [&](int kt, int s) {
        const uint32_t aB = sbase + s * STAGE_BH;
        const uint32_t bB = aB + TILE_BH;
        const int kh = kt * BKH + seg * 8;
        #pragma unroll
        for (int it = 0; it < 4; it++) {
            int r = sr + it * 32;
            cp16(aB + r * RSB + seg * 16, Ab + (size_t)r * K + kh);
            cp16(bB + r * RSB + seg * 16, Bb + (size_t)r * K + kh);
        }
    };

    stage(0, 0);
    cp_commit();

    for (int kt = 0; kt < NT; kt++) {
        if (kt + 1 < NT) stage(kt + 1, (kt + 1) & 1);
        cp_commit();
        cp_wait1();
        __syncthreads();

        const uint32_t aS = sbase + (kt & 1) * STAGE_BH;
        const uint32_t bS = aS + TILE_BH;

        #pragma unroll
        for (int s = 0; s < 4; s++) {
            const int kb = s * 32;
            uint32_t afr[2][4];
            #pragma unroll
            for (int mt = 0; mt < 2; mt++)
                ldm_x4(afr[mt], aS + (wm0 + mt * 16 + a_r) * RSB + kb + a_k);
            uint32_t bfr[8][2];
            #pragma unroll
            for (int jj = 0; jj < 4; jj++) {
                uint32_t r[4];
                ldm_x4(r, bS + (wn0 + jj * 16 + b_r) * RSB + kb + b_k);
                bfr[jj * 2 + 0][0] = r[0]; bfr[jj * 2 + 0][1] = r[1];
                bfr[jj * 2 + 1][0] = r[2]; bfr[jj * 2 + 1][1] = r[3];
            }
            #pragma unroll
            for (int mt = 0; mt < 2; mt++)
                #pragma unroll
                for (int j = 0; j < 8; j++)
                    mma_f16(acc[mt][j], afr[mt], bfr[j]);
        }
        __syncthreads();
    }

    if (c_sel == 1) {
        // Transposed epilogue: smem bounce [n=128][m=136 halves], then
        // coalesced 16B stores: 128 rows x 16 uint4-segments = 2048 uint4.
        __half* To = (__half*)g_dsmem;     // [128][136]
        #pragma unroll
        for (int mt = 0; mt < 2; mt++)
            #pragma unroll
            for (int e2 = 0; e2 < 2; e2++) {
                int m = wm0 + mt * 16 + grp + e2 * 8;
                #pragma unroll
                for (int j = 0; j < 8; j++) {
                    int n = wn0 + j * 8 + 2 * qid;
                    To[(n + 0) * 136 + m] = __float2half_rn(acc[mt][j][e2 * 2 + 0]);
                    To[(n + 1) * 136 + m] = __float2half_rn(acc[mt][j][e2 * 2 + 1]);
                }
            }
        __syncthreads();
        __half* base = g_qkvT + ((size_t)z * NPIX + n0) * MQKV + m0;
        #pragma unroll
        for (int i = 0; i < 8; i++) {
            int idx = tid + i * 256;        // 0..2047
            int n  = idx >> 4;              // 0..127
            int sg = idx & 15;              // 0..15
            uint4 val = *(uint4*)(To + n * 136 + sg * 8);
            *(uint4*)(base + (size_t)n * MQKV + sg * 8) = val;
        }
    } else {
        #pragma unroll
        for (int mt = 0; mt < 2; mt++)
            #pragma unroll
            for (int e2 = 0; e2 < 2; e2++) {
                int mloc = wm0 + mt * 16 + grp + e2 * 8;
                float bv = bias[m0 + mloc];
                #pragma unroll
                for (int j = 0; j < 8; j++) {
                    float2 r;
                    r.x = acc[mt][j][e2 * 2 + 0] + bv;
                    r.y = acc[mt][j][e2 * 2 + 1] + bv;
                    *(float2*)(Cf + (size_t)mloc * NPIX + wn0 + j * 8 + 2 * qid) = r;
                }
            }
    }
}

// ---------------------------------------------------------------------------
// 3x3 windowed attention — full-resident: ALL 16 chunks (k0..7, v0..7 = 87KB)
// staged in ONE cp.async burst (max MLP), one commit, wait_group 0, ONE
// __syncthreads, then all compute barrier-free from smem.
// Block = 8row x 32col slab of one (b,h). Tile = [10r][34c][8d] uint4/chunk;
// cp.async zfill covers halo/OOB -> exact zero-pad (OOB logit contribution 0).
// 2 blocks/SM (174KB), 512 blocks = 1.73 waves; load/compute overlap across
// blocks instead of within.
// ---------------------------------------------------------------------------
#define TPOS 340                          // 10*34 positions per chunk
#define ATT_SMEM (16 * TPOS * 16)         // 87040 B

__global__ void __launch_bounds__(256)
attn_kernel(float* __restrict__ attn_out)
{
    uint4* tk4 = (uint4*)g_dsmem;          // [8][340]  k chunks
    uint4* tv4 = tk4 + 8 * TPOS;           // [8][340]  v chunks

    const int tid  = threadIdx.x;
    const int lane = tid & 31;
    const int warp = tid >> 5;
    const int ry   = warp;                 // row within slab
    const int x    = lane;                 // col
    const int r0   = blockIdx.x * 8;
    const int h    = blockIdx.y;
    const int b    = blockIdx.z;
    const int p    = (r0 + ry) * 32 + x;

    const __half* __restrict__ qT = g_qkvT + ((size_t)(b * NPIX + p)) * MQKV + h * DH;
    const __half* __restrict__ kBase = g_qkvT + (size_t)b * NPIX * MQKV + 512 + h * DH;
    const __half* __restrict__ vBase = kBase + 512;

    const int bidx = ry * 34 + x;          // this thread's tile position

    // stage one chunk (dc..dc+7) of src (k or v) into dstbuf (uint4[340])
    auto stageChunk = [&](const __half* __restrict__ src, int dc, uint4* dstbuf) {
        const uint32_t dsb = (uint32_t)__cvta_generic_to_shared(dstbuf);
        #pragma unroll
        for (int rep = 0; rep < 2; rep++) {
            const int rr = warp + rep * 8;
            if (rep == 0 || warp < 2) {
                const int gy = r0 + rr - 1;
                const bool rok = ((unsigned)gy < 32u);
                {
                    const int gx = lane - 1;
                    const bool ok = rok && ((unsigned)gx < 32u);
                    const __half* s = src + (ok ? (size_t)(gy * 32 + gx) * MQKV : 0) + dc;
                    cp16z(dsb + (uint32_t)((rr * 34 + lane) * 16), s, ok);
                }
                if (lane < 2) {
                    const int gx = lane + 31;
                    const bool ok = rok && ((unsigned)gx < 32u);
                    const __half* s = src + (ok ? (size_t)(gy * 32 + gx) * MQKV : 0) + dc;
                    cp16z(dsb + (uint32_t)((rr * 34 + lane + 32) * 16), s, ok);
                }
            }
        }
    };

    // ---- Stage EVERYTHING: 16 chunks, one group, max memory parallelism ----
    #pragma unroll
    for (int c = 0; c < 8; c++) stageChunk(kBase, c * 8, tk4 + c * TPOS);
    #pragma unroll
    for (int c = 0; c < 8; c++) stageChunk(vBase, c * 8, tv4 + c * TPOS);
    cp_commit();
    cp_wait0();
    __syncthreads();        // the ONLY block barrier

    // window offsets in uint4 units
    const int WOFF[9] = {0, 1, 2, 34, 35, 36, 68, 69, 70};

    // ---------------- Pass 1: dots = q . k ----------------
    float dots[9];
    #pragma unroll
    for (int w = 0; w < 9; w++) dots[w] = 0.f;

    #pragma unroll
    for (int c = 0; c < 8; c++) {
        const uint4* kB = tk4 + c * TPOS;
        uint4 q4 = *(const uint4*)(qT + c * 8);
        half2 qh[4];
        *(uint4*)qh = q4;
        #pragma unroll
        for (int w = 0; w < 9; w++) {
            uint4 kv = kB[bidx + WOFF[w]];
            half2 kh[4];
            *(uint4*)kh = kv;
            half2 s = __hmul2(qh[0], kh[0]);
            s = __hfma2(qh[1], kh[1], s);
            s = __hfma2(qh[2], kh[2], s);
            s = __hfma2(qh[3], kh[3], s);
            float2 f = __half22float2(s);
            dots[w] += f.x + f.y;
        }
    }

    // softmax over 9 (OOB logits exactly 0)
    const float scale = 0.125f;
    float mx = -1e30f;
    #pragma unroll
    for (int w = 0; w < 9; w++) { dots[w] *= scale; mx = fmaxf(mx, dots[w]); }
    float a[9], sum = 0.f;
    #pragma unroll
    for (int w = 0; w < 9; w++) { a[w] = expf(dots[w] - mx); sum += a[w]; }
    float inv = 1.f / sum;
    #pragma unroll
    for (int w = 0; w < 9; w++) a[w] *= inv;

    {
        float* ao = attn_out + ((size_t)(b * HEADS + h) * NPIX + p) * 9;
        #pragma unroll
        for (int w = 0; w < 9; w++) ao[w] = a[w];
    }

    // ---------------- Pass 2: ctx = attn . v (barrier-free) ----------------
    __half* __restrict__ ct = g_ctxh + ((size_t)b * NPIX + p) * INNER + h * DH;

    #pragma unroll 2
    for (int c = 0; c < 8; c++) {
        const uint4* vB = tv4 + c * TPOS;
        float acc8[8];
        #pragma unroll
        for (int d = 0; d < 8; d++) acc8[d] = 0.f;
        #pragma unroll
        for (int w = 0; w < 9; w++) {
            uint4 vv = vB[bidx + WOFF[w]];
            half2 vh[4];
            *(uint4*)vh = vv;
            #pragma unroll
            for (int j = 0; j < 4; j++) {
                float2 f = __half22float2(vh[j]);
                acc8[2 * j + 0] += a[w] * f.x;
                acc8[2 * j + 1] += a[w] * f.y;
            }
        }
        half2 hout[4];
        #pragma unroll
        for (int j = 0; j < 4; j++)
            hout[j] = __floats2half2_rn(acc8[2 * j], acc8[2 * j + 1]);
        *(uint4*)(ct + c * 8) = *(uint4*)hout;
    }
}

// ---------------------------------------------------------------------------
extern "C" void kernel_launch(void* const* d_in, const int* in_sizes, int n_in,
                              void* d_out, int out_size)
{
    const float* x   = (const float*)d_in[0];
    const float* Wq  = (const float*)d_in[1];
    const float* Wkv = (const float*)d_in[2];
    const float* Wo  = (const float*)d_in[3];
    const float* bo  = (const float*)d_in[4];
    float* out = (float*)d_out;     // out (4194304) | attn (1179648)

    static int smem_set = 0;
    if (!smem_set) {
        cudaFuncSetAttribute(gemm_h, cudaFuncAttributeMaxDynamicSharedMemorySize,
                             SMEM_GH);
        cudaFuncSetAttribute(attn_kernel, cudaFuncAttributeMaxDynamicSharedMemorySize,
                             ATT_SMEM);
        smem_set = 1;
    }

    // prep: transpose+round x, round weights (fp16)
    {
        dim3 g(32, 8, BATCH);
        prep_x<<<g, 256>>>(x);
        prep_w<<<512, 256>>>(Wq, Wkv, Wo);
    }

    // QKV: g_qkvT[b][p][m] = g_wh[m][:] . g_xh[b][p][:]   (K=256, NT=4)
    {
        dim3 grid(NPIX / 128, MQKV / 128, BATCH);   // (8, 12, 16)
        gemm_h<<<grid, 256, SMEM_GH>>>(1, 1, nullptr, 1, nullptr, MQKV, CIN);
    }

    // attention -> attn tail + g_ctxh
    {
        dim3 grid(4, HEADS, BATCH);                 // 512 blocks
        attn_kernel<<<grid, 256, ATT_SMEM>>>(out + OUT_ELEMS);
    }

    // out projection: out[b][c][p] = g_woh[c][:] . g_ctxh[b][p][:] + bo[c]  (K=512, NT=8)
    {
        dim3 grid(NPIX / 128, CIN / 128, BATCH);    // (8, 2, 16)
        gemm_h<<<grid, 256, SMEM_GH>>>(2, 2, out, 0, bo, CIN, INNER);
    }
}